// round 1
// baseline (speedup 1.0000x reference)
#include <cuda_runtime.h>
#include <cuda_bf16.h>

// Problem dims (fixed by the reference setup)
#define BB   4
#define SS   2048
#define DIN  1024
#define HH   16
#define DK   64
#define DVH  64
#define DM   1024
#define MM   (BB * SS)          // 8192 rows of x / output
#define SCALE 0.125f            // 1/sqrt(64)

// ---------------------------------------------------------------------------
// Scratch (device globals; no allocation allowed in kernel_launch)
// ---------------------------------------------------------------------------
__device__ float g_Q[BB * HH * SS * DK];     // [B,H,S,DK]
__device__ float g_K[BB * HH * SS * DK];     // [B,H,S,DK]
__device__ float g_V[BB * HH * SS * DVH];    // [B,H,S,DVH]
__device__ float g_A[MM * HH * DVH];         // [B,S,H*DVH]  (concat layout)

// ---------------------------------------------------------------------------
// Kernel 1: per-head projection GEMM
//   out[b,h,s,k] = sum_d x[b,s,d] * W[h,d,k]
// grid: (MM/64, HH), block: 256 (16x16), 4x4 strided micro-tile
// ---------------------------------------------------------------------------
__global__ void proj_kernel(const float* __restrict__ x,
                            const float* __restrict__ W,
                            float* __restrict__ out)
{
    __shared__ float As[64][17];   // [row][k-chunk], pad to 17
    __shared__ float Bs[16][64];   // [k-chunk][col]

    const int m0 = blockIdx.x * 64;
    const int h  = blockIdx.y;
    const int tid = threadIdx.x;
    const int tx = tid & 15;
    const int ty = tid >> 4;

    const float* Wh = W + (size_t)h * DIN * DK;

    float acc[4][4];
#pragma unroll
    for (int r = 0; r < 4; r++)
#pragma unroll
        for (int c = 0; c < 4; c++) acc[r][c] = 0.0f;

    for (int kk = 0; kk < DIN; kk += 16) {
        // load A tile 64x16
#pragma unroll
        for (int it = 0; it < 4; it++) {
            int idx = tid + it * 256;
            int i = idx >> 4, j = idx & 15;
            As[i][j] = x[(size_t)(m0 + i) * DIN + kk + j];
        }
        // load B tile 16x64
#pragma unroll
        for (int it = 0; it < 4; it++) {
            int idx = tid + it * 256;
            int j = idx >> 6, n = idx & 63;
            Bs[j][n] = Wh[(size_t)(kk + j) * DK + n];
        }
        __syncthreads();

#pragma unroll
        for (int j = 0; j < 16; j++) {
            float a[4], b[4];
#pragma unroll
            for (int r = 0; r < 4; r++) a[r] = As[ty + 16 * r][j];
#pragma unroll
            for (int c = 0; c < 4; c++) b[c] = Bs[j][tx + 16 * c];
#pragma unroll
            for (int r = 0; r < 4; r++)
#pragma unroll
                for (int c = 0; c < 4; c++)
                    acc[r][c] += a[r] * b[c];
        }
        __syncthreads();
    }

    // write out in [B,H,S,DK] layout
#pragma unroll
    for (int r = 0; r < 4; r++) {
        int m = m0 + ty + 16 * r;
        int b = m >> 11;           // /SS
        int s = m & (SS - 1);
        float* orow = out + (((size_t)(b * HH + h) * SS + s) * DK);
#pragma unroll
        for (int c = 0; c < 4; c++)
            orow[tx + 16 * c] = acc[r][c];
    }
}

// ---------------------------------------------------------------------------
// Kernel 2: causal flash attention (fp32, online softmax)
// grid: (SS/64, HH, BB), block 256 (8 warps, 8 query rows each)
// dynamic smem: Qs[64*64] + Ks[64*65] + Vs[64*64] + Ps[8*8*64]
// ---------------------------------------------------------------------------
#define ATTN_SMEM_FLOATS (64 * 64 + 64 * 65 + 64 * 64 + 8 * 8 * 64)

__global__ void attn_kernel()
{
    extern __shared__ float sm[];
    float* Qs = sm;                       // [64][64]
    float* Ks = Qs + 64 * 64;             // [64][65]  (padded)
    float* Vs = Ks + 64 * 65;             // [64][64]
    float* Ps = Vs + 64 * 64;             // [8 warps][8 rows][64]

    const int q0 = blockIdx.x * 64;
    const int h  = blockIdx.y;
    const int b  = blockIdx.z;
    const int tid  = threadIdx.x;
    const int w    = tid >> 5;
    const int lane = tid & 31;

    const size_t bh = (size_t)(b * HH + h) * SS;
    const float* Qg = g_Q + (bh + q0) * DK;

    // load Q tile
    for (int idx = tid; idx < 64 * 64; idx += 256) {
        int r = idx >> 6, k = idx & 63;
        Qs[r * 64 + k] = Qg[(size_t)r * DK + k];
    }

    float m_i[8], l_i[8], accO[8][2];
#pragma unroll
    for (int r = 0; r < 8; r++) {
        m_i[r] = -1e30f; l_i[r] = 0.0f;
        accO[r][0] = 0.0f; accO[r][1] = 0.0f;
    }

    for (int k0 = 0; k0 <= q0; k0 += 64) {
        __syncthreads();   // protect Ks/Vs reuse + Q load on first iter
        const float* Kg = g_K + (bh + k0) * DK;
        const float* Vg = g_V + (bh + k0) * DVH;
        for (int idx = tid; idx < 64 * 64; idx += 256) {
            int r = idx >> 6, c = idx & 63;
            Ks[r * 65 + c] = Kg[(size_t)r * DK + c];
            Vs[r * 64 + c] = Vg[(size_t)r * DVH + c];
        }
        __syncthreads();

#pragma unroll
        for (int r = 0; r < 8; r++) {
            const int qrow  = w * 8 + r;
            const int qglob = q0 + qrow;
            const float* qp  = Qs + qrow * 64;
            const float* kp0 = Ks + lane * 65;
            const float* kp1 = Ks + (lane + 32) * 65;

            float s0 = 0.0f, s1 = 0.0f;
#pragma unroll
            for (int k = 0; k < 64; k++) {
                float q = qp[k];
                s0 += q * kp0[k];
                s1 += q * kp1[k];
            }
            s0 *= SCALE; s1 *= SCALE;
            if (k0 + lane      > qglob) s0 = -1e30f;
            if (k0 + lane + 32 > qglob) s1 = -1e30f;

            // row max across warp
            float mx = fmaxf(s0, s1);
#pragma unroll
            for (int off = 16; off > 0; off >>= 1)
                mx = fmaxf(mx, __shfl_xor_sync(0xffffffffu, mx, off));
            float m_new = fmaxf(m_i[r], mx);

            float p0 = __expf(s0 - m_new);
            float p1 = __expf(s1 - m_new);
            float psum = p0 + p1;
#pragma unroll
            for (int off = 16; off > 0; off >>= 1)
                psum += __shfl_xor_sync(0xffffffffu, psum, off);

            float alpha = __expf(m_i[r] - m_new);
            l_i[r] = l_i[r] * alpha + psum;
            m_i[r] = m_new;
            accO[r][0] *= alpha;
            accO[r][1] *= alpha;

            // stage probabilities for the PV accumulation
            float* prow = Ps + (w * 8 + r) * 64;
            prow[lane]      = p0;
            prow[lane + 32] = p1;
            __syncwarp();
#pragma unroll
            for (int c = 0; c < 64; c++) {
                float p = prow[c];
                accO[r][0] += p * Vs[c * 64 + lane];
                accO[r][1] += p * Vs[c * 64 + lane + 32];
            }
            __syncwarp();
        }
    }

    // normalize + write to concat layout [B,S,H*DVH]
#pragma unroll
    for (int r = 0; r < 8; r++) {
        int qrow = w * 8 + r;
        float inv = 1.0f / l_i[r];
        float* orow = g_A + ((size_t)(b * SS + q0 + qrow) * (HH * DVH)) + h * DVH;
        orow[lane]      = accO[r][0] * inv;
        orow[lane + 32] = accO[r][1] * inv;
    }
}

// ---------------------------------------------------------------------------
// Kernel 3: output projection  out[m,n] = sum_k A[m,k] * Wo[k,n]
// grid: (MM/64, DM/64), block 256, 4x4 strided micro-tile
// ---------------------------------------------------------------------------
__global__ void outproj_kernel(const float* __restrict__ Wo,
                               float* __restrict__ out)
{
    __shared__ float As[64][17];
    __shared__ float Bs[16][64];

    const int m0 = blockIdx.x * 64;
    const int n0 = blockIdx.y * 64;
    const int tid = threadIdx.x;
    const int tx = tid & 15;
    const int ty = tid >> 4;

    float acc[4][4];
#pragma unroll
    for (int r = 0; r < 4; r++)
#pragma unroll
        for (int c = 0; c < 4; c++) acc[r][c] = 0.0f;

    for (int kk = 0; kk < HH * DVH; kk += 16) {
#pragma unroll
        for (int it = 0; it < 4; it++) {
            int idx = tid + it * 256;
            int i = idx >> 4, j = idx & 15;
            As[i][j] = g_A[(size_t)(m0 + i) * (HH * DVH) + kk + j];
        }
#pragma unroll
        for (int it = 0; it < 4; it++) {
            int idx = tid + it * 256;
            int j = idx >> 6, n = idx & 63;
            Bs[j][n] = Wo[(size_t)(kk + j) * DM + n0 + n];
        }
        __syncthreads();

#pragma unroll
        for (int j = 0; j < 16; j++) {
            float a[4], bb[4];
#pragma unroll
            for (int r = 0; r < 4; r++) a[r] = As[ty + 16 * r][j];
#pragma unroll
            for (int c = 0; c < 4; c++) bb[c] = Bs[j][tx + 16 * c];
#pragma unroll
            for (int r = 0; r < 4; r++)
#pragma unroll
                for (int c = 0; c < 4; c++)
                    acc[r][c] += a[r] * bb[c];
        }
        __syncthreads();
    }

#pragma unroll
    for (int r = 0; r < 4; r++) {
        float* orow = out + (size_t)(m0 + ty + 16 * r) * DM + n0;
#pragma unroll
        for (int c = 0; c < 4; c++)
            orow[tx + 16 * c] = acc[r][c];
    }
}

// ---------------------------------------------------------------------------
// launch
// ---------------------------------------------------------------------------
extern "C" void kernel_launch(void* const* d_in, const int* in_sizes, int n_in,
                              void* d_out, int out_size)
{
    const float* x  = (const float*)d_in[0];
    const float* Wq = (const float*)d_in[1];
    const float* Wk = (const float*)d_in[2];
    const float* Wv = (const float*)d_in[3];
    const float* Wo = (const float*)d_in[4];
    float* out = (float*)d_out;

    float *pQ, *pK, *pV;
    cudaGetSymbolAddress((void**)&pQ, g_Q);
    cudaGetSymbolAddress((void**)&pK, g_K);
    cudaGetSymbolAddress((void**)&pV, g_V);

    static int smem_set = 0;
    const int attn_smem = ATTN_SMEM_FLOATS * (int)sizeof(float);
    if (!smem_set) {
        cudaFuncSetAttribute(attn_kernel,
                             cudaFuncAttributeMaxDynamicSharedMemorySize,
                             attn_smem);
        smem_set = 1;
    }

    dim3 pgrid(MM / 64, HH);
    proj_kernel<<<pgrid, 256>>>(x, Wq, pQ);
    proj_kernel<<<pgrid, 256>>>(x, Wk, pK);
    proj_kernel<<<pgrid, 256>>>(x, Wv, pV);

    dim3 agrid(SS / 64, HH, BB);
    attn_kernel<<<agrid, 256, attn_smem>>>();

    dim3 ogrid(MM / 64, DM / 64);
    outproj_kernel<<<ogrid, 256>>>(Wo, out);
}

// round 2
// speedup vs baseline: 1.8108x; 1.8108x over previous
#include <cuda_runtime.h>
#include <cuda_bf16.h>
#include <mma.h>

using namespace nvcuda;
typedef __nv_bfloat16 bf16;

// Problem dims (fixed by reference setup)
#define BB   4
#define SS   2048
#define DIN  1024
#define HH   16
#define DK   64
#define DVH  64
#define DM   1024
#define MM   (BB * SS)
#define SCALE 0.125f

// ---------------------------------------------------------------------------
// Scratch (device globals — no allocation allowed)
// ---------------------------------------------------------------------------
__device__ bf16 g_xh[MM * DIN],  g_xl[MM * DIN];
__device__ bf16 g_Wqh[HH * DIN * DK], g_Wql[HH * DIN * DK];
__device__ bf16 g_Wkh[HH * DIN * DK], g_Wkl[HH * DIN * DK];
__device__ bf16 g_Wvh[HH * DIN * DK], g_Wvl[HH * DIN * DK];
__device__ bf16 g_Woh[DM * DM],  g_Wol[DM * DM];
__device__ bf16 g_Qh[BB * HH * SS * DK], g_Ql[BB * HH * SS * DK];
__device__ bf16 g_Kh[BB * HH * SS * DK], g_Kl[BB * HH * SS * DK];
__device__ bf16 g_Vh[BB * HH * SS * DK], g_Vl[BB * HH * SS * DK];
__device__ bf16 g_Ah[MM * DM],  g_Al[MM * DM];

__device__ __forceinline__ void split2(float v, bf16& h, bf16& l)
{
    h = __float2bfloat16(v);
    l = __float2bfloat16(v - __bfloat162float(h));
}

// ---------------------------------------------------------------------------
// split conversion: fp32 -> (hi, lo) bf16
// ---------------------------------------------------------------------------
__global__ void split_kernel(const float* __restrict__ in,
                             bf16* __restrict__ hi, bf16* __restrict__ lo, int n)
{
    int i = blockIdx.x * 256 + threadIdx.x;
    if (i < n) {
        bf16 h, l;
        split2(in[i], h, l);
        hi[i] = h; lo[i] = l;
    }
}

// ---------------------------------------------------------------------------
// Projection GEMM (per head): C[128x64] tile = x[128xK] @ W_h[Kx64]
// grid (MM/128, HH), block 256 = 8 warps (4x2), warp tile 32x32 (2x2 frags)
// split-bf16: 3 mma per frag pair.  Output written as split bf16 [B,H,S,64].
// ---------------------------------------------------------------------------
__global__ void proj_wmma(const bf16* __restrict__ xh, const bf16* __restrict__ xl,
                          const bf16* __restrict__ Wh_, const bf16* __restrict__ Wl_,
                          bf16* __restrict__ Oh, bf16* __restrict__ Ol)
{
    __shared__ __align__(32) float Cs[128 * 72];   // epilogue tile; aliased below
    bf16* sAh = (bf16*)Cs;                 // [128][24] (16 valid cols)
    bf16* sAl = sAh + 128 * 24;
    bf16* sBh = sAl + 128 * 24;            // [16][72]  (64 valid cols)
    bf16* sBl = sBh + 16 * 72;

    const int m0  = blockIdx.x * 128;
    const int h   = blockIdx.y;
    const int tid = threadIdx.x;
    const int w   = tid >> 5;
    const int wm  = w >> 1;                // 0..3 -> rows wm*32
    const int wn  = w & 1;                 // 0..1 -> cols wn*32

    const bf16* Wh = Wh_ + (size_t)h * DIN * DK;
    const bf16* Wl = Wl_ + (size_t)h * DIN * DK;

    wmma::fragment<wmma::accumulator, 16, 16, 16, float> acc[2][2];
#pragma unroll
    for (int i = 0; i < 2; i++)
#pragma unroll
        for (int j = 0; j < 2; j++) wmma::fill_fragment(acc[i][j], 0.0f);

    for (int kk = 0; kk < DIN; kk += 16) {
        // A tile 128x16
        for (int idx = tid; idx < 128 * 16; idx += 256) {
            int r = idx >> 4, c = idx & 15;
            size_t g = (size_t)(m0 + r) * DIN + kk + c;
            sAh[r * 24 + c] = xh[g];
            sAl[r * 24 + c] = xl[g];
        }
        // B tile 16x64
        for (int idx = tid; idx < 16 * 64; idx += 256) {
            int r = idx >> 6, c = idx & 63;
            size_t g = (size_t)(kk + r) * DK + c;
            sBh[r * 72 + c] = Wh[g];
            sBl[r * 72 + c] = Wl[g];
        }
        __syncthreads();

        wmma::fragment<wmma::matrix_a, 16, 16, 16, bf16, wmma::row_major> ah[2], al[2];
#pragma unroll
        for (int i = 0; i < 2; i++) {
            wmma::load_matrix_sync(ah[i], sAh + (wm * 32 + i * 16) * 24, 24);
            wmma::load_matrix_sync(al[i], sAl + (wm * 32 + i * 16) * 24, 24);
        }
        wmma::fragment<wmma::matrix_b, 16, 16, 16, bf16, wmma::row_major> bh[2], bl[2];
#pragma unroll
        for (int j = 0; j < 2; j++) {
            wmma::load_matrix_sync(bh[j], sBh + wn * 32 + j * 16, 72);
            wmma::load_matrix_sync(bl[j], sBl + wn * 32 + j * 16, 72);
        }
#pragma unroll
        for (int i = 0; i < 2; i++)
#pragma unroll
            for (int j = 0; j < 2; j++) {
                wmma::mma_sync(acc[i][j], ah[i], bh[j], acc[i][j]);
                wmma::mma_sync(acc[i][j], al[i], bh[j], acc[i][j]);
                wmma::mma_sync(acc[i][j], ah[i], bl[j], acc[i][j]);
            }
        __syncthreads();
    }

    // epilogue: frags -> Cs -> split bf16 global in [B,H,S,64]
#pragma unroll
    for (int i = 0; i < 2; i++)
#pragma unroll
        for (int j = 0; j < 2; j++)
            wmma::store_matrix_sync(Cs + (wm * 32 + i * 16) * 72 + wn * 32 + j * 16,
                                    acc[i][j], 72, wmma::mem_row_major);
    __syncthreads();

    for (int idx = tid; idx < 128 * 64; idx += 256) {
        int r = idx >> 6, c = idx & 63;
        int m = m0 + r;
        int b = m >> 11;
        int s = m & (SS - 1);
        size_t dst = ((size_t)(b * HH + h) * SS + s) * DK + c;
        bf16 hh, ll;
        split2(Cs[r * 72 + c], hh, ll);
        Oh[dst] = hh; Ol[dst] = ll;
    }
}

// ---------------------------------------------------------------------------
// Flash attention with wmma GEMMs (split-bf16), online softmax in fp32.
// grid (SS/64, HH, BB), block 256.  Dynamic smem layout (bytes):
//   Qh,Ql,Kh,Kl,Vh,Vl : 6 * 64*72*2 = 55296
//   S  (fp32)         : 64*72*4     = 18432   @55296
//   Ph,Pl             : 2 * 9216    = 18432   @73728
//   O  (fp32)         : 18432                 @92160
// total 110592 B
// ---------------------------------------------------------------------------
#define ATTN_SMEM_BYTES 110592

__global__ void attn_wmma()
{
    extern __shared__ __align__(32) char smraw[];
    bf16*  sQh = (bf16*)smraw;
    bf16*  sQl = sQh + 64 * 72;
    bf16*  sKh = sQl + 64 * 72;
    bf16*  sKl = sKh + 64 * 72;
    bf16*  sVh = sKl + 64 * 72;
    bf16*  sVl = sVh + 64 * 72;
    float* sS  = (float*)(smraw + 55296);
    bf16*  sPh = (bf16*)(smraw + 73728);
    bf16*  sPl = sPh + 64 * 72;
    float* sO  = (float*)(smraw + 92160);

    const int q0  = blockIdx.x * 64;
    const int h   = blockIdx.y;
    const int b   = blockIdx.z;
    const int tid = threadIdx.x;
    const int w   = tid >> 5;
    const int wm  = w >> 1;     // 0..3
    const int wn  = w & 1;      // 0..1

    const int row = tid >> 2;   // 0..63 (softmax ownership)
    const int sub = tid & 3;    // 4 threads per row, 16 cols each

    const size_t bh = (size_t)(b * HH + h) * SS;

    // init O = 0, load Q tile
    for (int idx = tid; idx < 64 * 72; idx += 256) sO[idx] = 0.0f;
    for (int idx = tid; idx < 64 * 64; idx += 256) {
        int r = idx >> 6, c = idx & 63;
        size_t g = (bh + q0 + r) * DK + c;
        sQh[r * 72 + c] = g_Qh[g];
        sQl[r * 72 + c] = g_Ql[g];
    }

    float m_i = -1e30f, l_i = 0.0f;

    for (int k0 = 0; k0 <= q0; k0 += 64) {
        __syncthreads();   // prev-iter PV done; Q/O init done (first iter)

        for (int idx = tid; idx < 64 * 64; idx += 256) {
            int r = idx >> 6, c = idx & 63;
            size_t g = (bh + k0 + r) * DK + c;
            sKh[r * 72 + c] = g_Kh[g];
            sKl[r * 72 + c] = g_Kl[g];
            sVh[r * 72 + c] = g_Vh[g];
            sVl[r * 72 + c] = g_Vl[g];
        }
        __syncthreads();

        // ---- S = Q @ K^T  (warp: rows wm*16, cols wn*32, 2 n-frags) ----
        {
            wmma::fragment<wmma::accumulator, 16, 16, 16, float> sacc[2];
            wmma::fill_fragment(sacc[0], 0.0f);
            wmma::fill_fragment(sacc[1], 0.0f);
#pragma unroll
            for (int kk = 0; kk < 4; kk++) {
                wmma::fragment<wmma::matrix_a, 16, 16, 16, bf16, wmma::row_major> qh, ql;
                wmma::load_matrix_sync(qh, sQh + (wm * 16) * 72 + kk * 16, 72);
                wmma::load_matrix_sync(ql, sQl + (wm * 16) * 72 + kk * 16, 72);
#pragma unroll
                for (int j = 0; j < 2; j++) {
                    wmma::fragment<wmma::matrix_b, 16, 16, 16, bf16, wmma::col_major> kh, kl;
                    wmma::load_matrix_sync(kh, sKh + (wn * 32 + j * 16) * 72 + kk * 16, 72);
                    wmma::load_matrix_sync(kl, sKl + (wn * 32 + j * 16) * 72 + kk * 16, 72);
                    wmma::mma_sync(sacc[j], qh, kh, sacc[j]);
                    wmma::mma_sync(sacc[j], ql, kh, sacc[j]);
                    wmma::mma_sync(sacc[j], qh, kl, sacc[j]);
                }
            }
#pragma unroll
            for (int j = 0; j < 2; j++)
                wmma::store_matrix_sync(sS + (wm * 16) * 72 + wn * 32 + j * 16,
                                        sacc[j], 72, wmma::mem_row_major);
        }
        __syncthreads();

        // ---- softmax (4 threads/row, 16 cols each) ----
        {
            const int qglob = q0 + row;
            float sv[16];
            float mx = -1e30f;
#pragma unroll
            for (int i = 0; i < 16; i++) {
                int c = sub * 16 + i;
                float s = sS[row * 72 + c] * SCALE;
                if (k0 + c > qglob) s = -1e30f;
                sv[i] = s;
                mx = fmaxf(mx, s);
            }
            mx = fmaxf(mx, __shfl_xor_sync(0xffffffffu, mx, 1));
            mx = fmaxf(mx, __shfl_xor_sync(0xffffffffu, mx, 2));
            float m_new = fmaxf(m_i, mx);
            float alpha = __expf(m_i - m_new);

            float psum = 0.0f;
#pragma unroll
            for (int i = 0; i < 16; i++) {
                int c = sub * 16 + i;
                float p = __expf(sv[i] - m_new);
                psum += p;
                bf16 ph, pl;
                split2(p, ph, pl);
                sPh[row * 72 + c] = ph;
                sPl[row * 72 + c] = pl;
            }
            psum += __shfl_xor_sync(0xffffffffu, psum, 1);
            psum += __shfl_xor_sync(0xffffffffu, psum, 2);

            l_i = l_i * alpha + psum;
            m_i = m_new;

            // rescale O rows (this thread group owns the row exclusively here)
#pragma unroll
            for (int i = 0; i < 16; i++)
                sO[row * 72 + sub * 16 + i] *= alpha;
        }
        __syncthreads();

        // ---- O += P @ V ----
        {
            wmma::fragment<wmma::accumulator, 16, 16, 16, float> oacc[2];
#pragma unroll
            for (int j = 0; j < 2; j++)
                wmma::load_matrix_sync(oacc[j], sO + (wm * 16) * 72 + wn * 32 + j * 16,
                                       72, wmma::mem_row_major);
#pragma unroll
            for (int kk = 0; kk < 4; kk++) {
                wmma::fragment<wmma::matrix_a, 16, 16, 16, bf16, wmma::row_major> ph, pl;
                wmma::load_matrix_sync(ph, sPh + (wm * 16) * 72 + kk * 16, 72);
                wmma::load_matrix_sync(pl, sPl + (wm * 16) * 72 + kk * 16, 72);
#pragma unroll
                for (int j = 0; j < 2; j++) {
                    wmma::fragment<wmma::matrix_b, 16, 16, 16, bf16, wmma::row_major> vh, vl;
                    wmma::load_matrix_sync(vh, sVh + (kk * 16) * 72 + wn * 32 + j * 16, 72);
                    wmma::load_matrix_sync(vl, sVl + (kk * 16) * 72 + wn * 32 + j * 16, 72);
                    wmma::mma_sync(oacc[j], ph, vh, oacc[j]);
                    wmma::mma_sync(oacc[j], ph, vl, oacc[j]);
                    wmma::mma_sync(oacc[j], pl, vh, oacc[j]);
                }
            }
#pragma unroll
            for (int j = 0; j < 2; j++)
                wmma::store_matrix_sync(sO + (wm * 16) * 72 + wn * 32 + j * 16,
                                        oacc[j], 72, wmma::mem_row_major);
        }
    }
    __syncthreads();

    // epilogue: normalize, split-write to concat layout [B,S, H*64]
    {
        float inv = 1.0f / l_i;
#pragma unroll
        for (int i = 0; i < 16; i++) {
            int c = sub * 16 + i;
            float v = sO[row * 72 + c] * inv;
            bf16 hh, ll;
            split2(v, hh, ll);
            size_t dst = ((size_t)(b * SS + q0 + row)) * DM + h * DVH + c;
            g_Ah[dst] = hh;
            g_Al[dst] = ll;
        }
    }
}

// ---------------------------------------------------------------------------
// Output projection: out[8192x1024] = A[8192x1024] @ Wo[1024x1024]
// grid (MM/128, DM/128), block 256 = 8 warps (4x2), warp tile 32x64 (2x4 frags)
// ---------------------------------------------------------------------------
__global__ void outproj_wmma(float* __restrict__ out)
{
    __shared__ __align__(32) bf16 sAh[128 * 24];
    __shared__ __align__(32) bf16 sAl[128 * 24];
    __shared__ __align__(32) bf16 sBh[16 * 136];
    __shared__ __align__(32) bf16 sBl[16 * 136];

    const int m0  = blockIdx.x * 128;
    const int n0  = blockIdx.y * 128;
    const int tid = threadIdx.x;
    const int w   = tid >> 5;
    const int wm  = w >> 1;     // rows wm*32
    const int wn  = w & 1;      // cols wn*64

    wmma::fragment<wmma::accumulator, 16, 16, 16, float> acc[2][4];
#pragma unroll
    for (int i = 0; i < 2; i++)
#pragma unroll
        for (int j = 0; j < 4; j++) wmma::fill_fragment(acc[i][j], 0.0f);

    for (int kk = 0; kk < DM; kk += 16) {
        for (int idx = tid; idx < 128 * 16; idx += 256) {
            int r = idx >> 4, c = idx & 15;
            size_t g = (size_t)(m0 + r) * DM + kk + c;
            sAh[r * 24 + c] = g_Ah[g];
            sAl[r * 24 + c] = g_Al[g];
        }
        for (int idx = tid; idx < 16 * 128; idx += 256) {
            int r = idx >> 7, c = idx & 127;
            size_t g = (size_t)(kk + r) * DM + n0 + c;
            sBh[r * 136 + c] = g_Woh[g];
            sBl[r * 136 + c] = g_Wol[g];
        }
        __syncthreads();

        wmma::fragment<wmma::matrix_a, 16, 16, 16, bf16, wmma::row_major> ah[2], al[2];
#pragma unroll
        for (int i = 0; i < 2; i++) {
            wmma::load_matrix_sync(ah[i], sAh + (wm * 32 + i * 16) * 24, 24);
            wmma::load_matrix_sync(al[i], sAl + (wm * 32 + i * 16) * 24, 24);
        }
#pragma unroll
        for (int j = 0; j < 4; j++) {
            wmma::fragment<wmma::matrix_b, 16, 16, 16, bf16, wmma::row_major> bh, bl;
            wmma::load_matrix_sync(bh, sBh + wn * 64 + j * 16, 136);
            wmma::load_matrix_sync(bl, sBl + wn * 64 + j * 16, 136);
#pragma unroll
            for (int i = 0; i < 2; i++) {
                wmma::mma_sync(acc[i][j], ah[i], bh, acc[i][j]);
                wmma::mma_sync(acc[i][j], al[i], bh, acc[i][j]);
                wmma::mma_sync(acc[i][j], ah[i], bl, acc[i][j]);
            }
        }
        __syncthreads();
    }

#pragma unroll
    for (int i = 0; i < 2; i++)
#pragma unroll
        for (int j = 0; j < 4; j++)
            wmma::store_matrix_sync(out + (size_t)(m0 + wm * 32 + i * 16) * DM
                                        + n0 + wn * 64 + j * 16,
                                    acc[i][j], DM, wmma::mem_row_major);
}

// ---------------------------------------------------------------------------
// launch
// ---------------------------------------------------------------------------
extern "C" void kernel_launch(void* const* d_in, const int* in_sizes, int n_in,
                              void* d_out, int out_size)
{
    const float* x  = (const float*)d_in[0];
    const float* Wq = (const float*)d_in[1];
    const float* Wk = (const float*)d_in[2];
    const float* Wv = (const float*)d_in[3];
    const float* Wo = (const float*)d_in[4];
    float* out = (float*)d_out;

    bf16 *xh, *xl, *wqh, *wql, *wkh, *wkl, *wvh, *wvl, *woh, *wol;
    bf16 *qh, *ql, *kh, *kl, *vh, *vl;
    cudaGetSymbolAddress((void**)&xh,  g_xh);  cudaGetSymbolAddress((void**)&xl,  g_xl);
    cudaGetSymbolAddress((void**)&wqh, g_Wqh); cudaGetSymbolAddress((void**)&wql, g_Wql);
    cudaGetSymbolAddress((void**)&wkh, g_Wkh); cudaGetSymbolAddress((void**)&wkl, g_Wkl);
    cudaGetSymbolAddress((void**)&wvh, g_Wvh); cudaGetSymbolAddress((void**)&wvl, g_Wvl);
    cudaGetSymbolAddress((void**)&woh, g_Woh); cudaGetSymbolAddress((void**)&wol, g_Wol);
    cudaGetSymbolAddress((void**)&qh,  g_Qh);  cudaGetSymbolAddress((void**)&ql,  g_Ql);
    cudaGetSymbolAddress((void**)&kh,  g_Kh);  cudaGetSymbolAddress((void**)&kl,  g_Kl);
    cudaGetSymbolAddress((void**)&vh,  g_Vh);  cudaGetSymbolAddress((void**)&vl,  g_Vl);

    static int smem_set = 0;
    if (!smem_set) {
        cudaFuncSetAttribute(attn_wmma,
                             cudaFuncAttributeMaxDynamicSharedMemorySize,
                             ATTN_SMEM_BYTES);
        smem_set = 1;
    }

    // split conversions
    {
        int n = MM * DIN;
        split_kernel<<<(n + 255) / 256, 256>>>(x, xh, xl, n);
        n = HH * DIN * DK;
        split_kernel<<<(n + 255) / 256, 256>>>(Wq, wqh, wql, n);
        split_kernel<<<(n + 255) / 256, 256>>>(Wk, wkh, wkl, n);
        split_kernel<<<(n + 255) / 256, 256>>>(Wv, wvh, wvl, n);
        n = DM * DM;
        split_kernel<<<(n + 255) / 256, 256>>>(Wo, woh, wol, n);
    }

    dim3 pgrid(MM / 128, HH);
    proj_wmma<<<pgrid, 256>>>(xh, xl, wqh, wql, qh, ql);
    proj_wmma<<<pgrid, 256>>>(xh, xl, wkh, wkl, kh, kl);
    proj_wmma<<<pgrid, 256>>>(xh, xl, wvh, wvl, vh, vl);

    dim3 agrid(SS / 64, HH, BB);
    attn_wmma<<<agrid, 256, ATTN_SMEM_BYTES>>>();

    dim3 ogrid(MM / 128, DM / 128);
    outproj_wmma<<<ogrid, 256>>>(out);
}

// round 10
// speedup vs baseline: 2.4224x; 1.3377x over previous
#include <cuda_runtime.h>
#include <cuda_bf16.h>
#include <mma.h>
#include <cstdint>

using namespace nvcuda;
typedef __nv_bfloat16 bf16;

// Problem dims
#define BB   4
#define SS   2048
#define DIN  1024
#define HH   16
#define DK   64
#define DVH  64
#define DM   1024
#define MM   (BB * SS)
#define SCALE 0.125f

// ---------------------------------------------------------------------------
// Scratch (device globals — no allocation allowed)
// ---------------------------------------------------------------------------
__device__ bf16 g_xh[MM * DIN],  g_xl[MM * DIN];
__device__ bf16 g_Wqh[HH * DIN * DK], g_Wql[HH * DIN * DK];   // [h][k][n]
__device__ bf16 g_Wkh[HH * DIN * DK], g_Wkl[HH * DIN * DK];
__device__ bf16 g_Wvh[HH * DIN * DK], g_Wvl[HH * DIN * DK];
__device__ bf16 g_Woh[DM * DM],  g_Wol[DM * DM];              // [k][n]
__device__ bf16 g_Qh[BB * HH * SS * DK], g_Ql[BB * HH * SS * DK];
__device__ bf16 g_Kh[BB * HH * SS * DK], g_Kl[BB * HH * SS * DK];
__device__ bf16 g_Vh[BB * HH * SS * DK], g_Vl[BB * HH * SS * DK];
__device__ bf16 g_Ah[MM * DM],  g_Al[MM * DM];                // [B*S][H*64]

__device__ __forceinline__ void split2(float v, bf16& h, bf16& l)
{
    h = __float2bfloat16(v);
    l = __float2bfloat16(v - __bfloat162float(h));
}

// ---------------------------------------------------------------------------
// elementwise split: fp32 -> (hi, lo) bf16
// ---------------------------------------------------------------------------
__global__ void split_kernel(const float* __restrict__ in,
                             bf16* __restrict__ hi, bf16* __restrict__ lo, int n)
{
    int i = blockIdx.x * 256 + threadIdx.x;
    if (i < n) {
        bf16 h, l;
        split2(in[i], h, l);
        hi[i] = h; lo[i] = l;
    }
}

// ---------------------------------------------------------------------------
// Fused QKV projection.
// Block tile: 128 rows (of x) x 64 cols (head dim), one head per blockIdx.y.
// 8 warps (4x2), warp tile 32x32.  K-chunk 32.  x A-tile staged ONCE per chunk
// and reused for Wq, Wk, Wv (3 accumulator sets).
// smem: sAh[128][40] | sAl[128][40] | 3 x (sBh[32][72] | sBl[32][72])
//       = 20480 + 27648 = 48128 B.  Epilogue aliases a float[128][72] buffer.
// ---------------------------------------------------------------------------
#define QKV_SMEM_BYTES 48128

__global__ __launch_bounds__(256) void qkv_wmma()
{
    extern __shared__ __align__(16) char sm[];
    bf16* sAh = (bf16*)sm;                // 128*40
    bf16* sAl = sAh + 128 * 40;
    bf16* sB  = sAl + 128 * 40;           // [3][2][32*72] (hi, lo per weight)
    float* fbuf = (float*)sm;             // epilogue [128][72]

    const int m0  = blockIdx.x * 128;
    const int h   = blockIdx.y;
    const int tid = threadIdx.x;
    const int w   = tid >> 5;
    const int wm  = w >> 1;               // 0..3 -> rows wm*32
    const int wn  = w & 1;                // 0..1 -> cols wn*32

    const bf16* Wh[3] = { g_Wqh + (size_t)h * DIN * DK,
                          g_Wkh + (size_t)h * DIN * DK,
                          g_Wvh + (size_t)h * DIN * DK };
    const bf16* Wl[3] = { g_Wql + (size_t)h * DIN * DK,
                          g_Wkl + (size_t)h * DIN * DK,
                          g_Wvl + (size_t)h * DIN * DK };

    wmma::fragment<wmma::accumulator, 16, 16, 16, float> acc[3][2][2];
#pragma unroll
    for (int g = 0; g < 3; g++)
#pragma unroll
        for (int i = 0; i < 2; i++)
#pragma unroll
            for (int j = 0; j < 2; j++) wmma::fill_fragment(acc[g][i][j], 0.0f);

    for (int kk = 0; kk < DIN; kk += 32) {
        // A tile 128x32 hi/lo: 512 uint4 per plane, 256 threads -> 2 each
#pragma unroll
        for (int it = 0; it < 2; it++) {
            int idx = tid + it * 256;
            int r = idx >> 2, c = idx & 3;
            size_t g = (size_t)(m0 + r) * DIN + kk + c * 8;
            *(uint4*)(sAh + r * 40 + c * 8) = *(const uint4*)(g_xh + g);
            *(uint4*)(sAl + r * 40 + c * 8) = *(const uint4*)(g_xl + g);
        }
        // B tiles: 3 weights x 32x64 hi/lo: 256 uint4 per plane
        {
            int j = tid >> 3, c = tid & 7;
            size_t g = (size_t)(kk + j) * DK + c * 8;
#pragma unroll
            for (int wgt = 0; wgt < 3; wgt++) {
                bf16* dh = sB + wgt * 2 * 32 * 72;
                bf16* dl = dh + 32 * 72;
                *(uint4*)(dh + j * 72 + c * 8) = *(const uint4*)(Wh[wgt] + g);
                *(uint4*)(dl + j * 72 + c * 8) = *(const uint4*)(Wl[wgt] + g);
            }
        }
        __syncthreads();

#pragma unroll
        for (int ks = 0; ks < 2; ks++) {
            wmma::fragment<wmma::matrix_a, 16, 16, 16, bf16, wmma::row_major> ah[2], al[2];
#pragma unroll
            for (int i = 0; i < 2; i++) {
                wmma::load_matrix_sync(ah[i], sAh + (wm * 32 + i * 16) * 40 + ks * 16, 40);
                wmma::load_matrix_sync(al[i], sAl + (wm * 32 + i * 16) * 40 + ks * 16, 40);
            }
#pragma unroll
            for (int wgt = 0; wgt < 3; wgt++) {
                const bf16* bh_base = sB + wgt * 2 * 32 * 72;
                const bf16* bl_base = bh_base + 32 * 72;
                wmma::fragment<wmma::matrix_b, 16, 16, 16, bf16, wmma::row_major> bh[2], bl[2];
#pragma unroll
                for (int j = 0; j < 2; j++) {
                    wmma::load_matrix_sync(bh[j], bh_base + ks * 16 * 72 + wn * 32 + j * 16, 72);
                    wmma::load_matrix_sync(bl[j], bl_base + ks * 16 * 72 + wn * 32 + j * 16, 72);
                }
#pragma unroll
                for (int i = 0; i < 2; i++)
#pragma unroll
                    for (int j = 0; j < 2; j++) {
                        wmma::mma_sync(acc[wgt][i][j], ah[i], bh[j], acc[wgt][i][j]);
                        wmma::mma_sync(acc[wgt][i][j], al[i], bh[j], acc[wgt][i][j]);
                        wmma::mma_sync(acc[wgt][i][j], ah[i], bl[j], acc[wgt][i][j]);
                    }
            }
        }
        __syncthreads();
    }

    // epilogue: 3 weights sequentially through the float buffer
    bf16* Oh_[3] = { g_Qh, g_Kh, g_Vh };
    bf16* Ol_[3] = { g_Ql, g_Kl, g_Vl };
#pragma unroll
    for (int wgt = 0; wgt < 3; wgt++) {
#pragma unroll
        for (int i = 0; i < 2; i++)
#pragma unroll
            for (int j = 0; j < 2; j++)
                wmma::store_matrix_sync(fbuf + (wm * 32 + i * 16) * 72 + wn * 32 + j * 16,
                                        acc[wgt][i][j], 72, wmma::mem_row_major);
        __syncthreads();
        for (int idx = tid; idx < 128 * 64; idx += 256) {
            int r = idx >> 6, c = idx & 63;
            int m = m0 + r;
            int b = m >> 11, s = m & (SS - 1);
            size_t dst = (((size_t)(b * HH + h)) * SS + s) * DK + c;
            bf16 hh, ll;
            split2(fbuf[r * 72 + c], hh, ll);
            Oh_[wgt][dst] = hh;
            Ol_[wgt][dst] = ll;
        }
        __syncthreads();
    }
}

// ---------------------------------------------------------------------------
// Output projection: out[8192x1024] = A @ Wo.  Block tile 128x128,
// 8 warps (4x2), warp tile 32x64, K-chunk 32.
// smem: sAh[128][40] sAl[128][40] sBh[32][136] sBl[32][136] = 37888 B
// ---------------------------------------------------------------------------
#define OUT_SMEM_BYTES 37888

__global__ __launch_bounds__(256) void outproj_wmma(float* __restrict__ out)
{
    extern __shared__ __align__(16) char sm[];
    bf16* sAh = (bf16*)sm;
    bf16* sAl = sAh + 128 * 40;
    bf16* sBh = sAl + 128 * 40;
    bf16* sBl = sBh + 32 * 136;

    const int m0  = blockIdx.x * 128;
    const int n0  = blockIdx.y * 128;
    const int tid = threadIdx.x;
    const int w   = tid >> 5;
    const int wm  = w >> 1;               // rows wm*32
    const int wn  = w & 1;                // cols wn*64

    wmma::fragment<wmma::accumulator, 16, 16, 16, float> acc[2][4];
#pragma unroll
    for (int i = 0; i < 2; i++)
#pragma unroll
        for (int j = 0; j < 4; j++) wmma::fill_fragment(acc[i][j], 0.0f);

    for (int kk = 0; kk < DM; kk += 32) {
        // A tile 128x32 hi/lo
#pragma unroll
        for (int it = 0; it < 2; it++) {
            int idx = tid + it * 256;
            int r = idx >> 2, c = idx & 3;
            size_t g = (size_t)(m0 + r) * DM + kk + c * 8;
            *(uint4*)(sAh + r * 40 + c * 8) = *(const uint4*)(g_Ah + g);
            *(uint4*)(sAl + r * 40 + c * 8) = *(const uint4*)(g_Al + g);
        }
        // B tile 32x128 hi/lo: 512 uint4 per plane
#pragma unroll
        for (int it = 0; it < 2; it++) {
            int idx = tid + it * 256;
            int j = idx >> 4, c = idx & 15;
            size_t g = (size_t)(kk + j) * DM + n0 + c * 8;
            *(uint4*)(sBh + j * 136 + c * 8) = *(const uint4*)(g_Woh + g);
            *(uint4*)(sBl + j * 136 + c * 8) = *(const uint4*)(g_Wol + g);
        }
        __syncthreads();

#pragma unroll
        for (int ks = 0; ks < 2; ks++) {
            wmma::fragment<wmma::matrix_a, 16, 16, 16, bf16, wmma::row_major> ah[2], al[2];
#pragma unroll
            for (int i = 0; i < 2; i++) {
                wmma::load_matrix_sync(ah[i], sAh + (wm * 32 + i * 16) * 40 + ks * 16, 40);
                wmma::load_matrix_sync(al[i], sAl + (wm * 32 + i * 16) * 40 + ks * 16, 40);
            }
#pragma unroll
            for (int j = 0; j < 4; j++) {
                wmma::fragment<wmma::matrix_b, 16, 16, 16, bf16, wmma::row_major> bh, bl;
                wmma::load_matrix_sync(bh, sBh + ks * 16 * 136 + wn * 64 + j * 16, 136);
                wmma::load_matrix_sync(bl, sBl + ks * 16 * 136 + wn * 64 + j * 16, 136);
#pragma unroll
                for (int i = 0; i < 2; i++) {
                    wmma::mma_sync(acc[i][j], ah[i], bh, acc[i][j]);
                    wmma::mma_sync(acc[i][j], al[i], bh, acc[i][j]);
                    wmma::mma_sync(acc[i][j], ah[i], bl, acc[i][j]);
                }
            }
        }
        __syncthreads();
    }

#pragma unroll
    for (int i = 0; i < 2; i++)
#pragma unroll
        for (int j = 0; j < 4; j++)
            wmma::store_matrix_sync(out + (size_t)(m0 + wm * 32 + i * 16) * DM
                                        + n0 + wn * 64 + j * 16,
                                    acc[i][j], DM, wmma::mem_row_major);
}

// ---------------------------------------------------------------------------
// Flash attention, Q-tile 128 x key-tile 64, 8 warps (4x2), warp tile 32x32.
// Online softmax fp32, split-bf16 MMAs.  smem layout (bytes):
//   sQh 0      (18432)   sQl 18432   sKh 36864 (9216)  sKl 46080
//   sVh 55296  (9216)    sVl 64512
//   sS  73728  (float 128x72 = 36864)
//   sPh 110592 (18432)   sPl 129024
//   sO  147456 (float 128x72 = 36864)   total 184320
// ---------------------------------------------------------------------------
#define ATTN_SMEM_BYTES 184320

__global__ __launch_bounds__(256) void attn_wmma()
{
    extern __shared__ __align__(16) char smraw[];
    bf16*  sQh = (bf16*)smraw;
    bf16*  sQl = sQh + 128 * 72;
    bf16*  sKh = (bf16*)(smraw + 36864);
    bf16*  sKl = sKh + 64 * 72;
    bf16*  sVh = (bf16*)(smraw + 55296);
    bf16*  sVl = sVh + 64 * 72;
    float* sS  = (float*)(smraw + 73728);
    bf16*  sPh = (bf16*)(smraw + 110592);
    bf16*  sPl = sPh + 128 * 72;
    float* sO  = (float*)(smraw + 147456);

    const int q0  = blockIdx.x * 128;
    const int h   = blockIdx.y;
    const int b   = blockIdx.z;
    const int tid = threadIdx.x;
    const int w   = tid >> 5;
    const int wm  = w >> 1;       // 0..3 -> S rows wm*32
    const int wn  = w & 1;        // 0..1 -> S cols wn*32

    const int row = tid >> 1;     // 0..127 (softmax: 2 threads per row)
    const int sub = tid & 1;      // 32 cols each

    const size_t bh = (size_t)(b * HH + h) * SS;

    // init O = 0, load Q tile (128x64 hi/lo)
    for (int idx = tid; idx < 128 * 72; idx += 256) sO[idx] = 0.0f;
    for (int idx = tid; idx < 128 * 64; idx += 256) {
        int r = idx >> 6, c = idx & 63;
        size_t g = (bh + q0 + r) * DK + c;
        sQh[r * 72 + c] = g_Qh[g];
        sQl[r * 72 + c] = g_Ql[g];
    }

    float m_i = -1e30f, l_i = 0.0f;

    for (int k0 = 0; k0 <= q0 + 64; k0 += 64) {
        __syncthreads();   // prev PV done / initial loads done

        for (int idx = tid; idx < 64 * 64; idx += 256) {
            int r = idx >> 6, c = idx & 63;
            size_t g = (bh + k0 + r) * DK + c;
            sKh[r * 72 + c] = g_Kh[g];
            sKl[r * 72 + c] = g_Kl[g];
            sVh[r * 72 + c] = g_Vh[g];
            sVl[r * 72 + c] = g_Vl[g];
        }
        __syncthreads();

        // ---- S = Q @ K^T ----
        {
            wmma::fragment<wmma::accumulator, 16, 16, 16, float> sacc[2][2];
#pragma unroll
            for (int i = 0; i < 2; i++)
#pragma unroll
                for (int j = 0; j < 2; j++) wmma::fill_fragment(sacc[i][j], 0.0f);
#pragma unroll
            for (int kk = 0; kk < 4; kk++) {
                wmma::fragment<wmma::matrix_a, 16, 16, 16, bf16, wmma::row_major> qh[2], ql[2];
#pragma unroll
                for (int i = 0; i < 2; i++) {
                    wmma::load_matrix_sync(qh[i], sQh + (wm * 32 + i * 16) * 72 + kk * 16, 72);
                    wmma::load_matrix_sync(ql[i], sQl + (wm * 32 + i * 16) * 72 + kk * 16, 72);
                }
#pragma unroll
                for (int j = 0; j < 2; j++) {
                    wmma::fragment<wmma::matrix_b, 16, 16, 16, bf16, wmma::col_major> kh, kl;
                    wmma::load_matrix_sync(kh, sKh + (wn * 32 + j * 16) * 72 + kk * 16, 72);
                    wmma::load_matrix_sync(kl, sKl + (wn * 32 + j * 16) * 72 + kk * 16, 72);
#pragma unroll
                    for (int i = 0; i < 2; i++) {
                        wmma::mma_sync(sacc[i][j], qh[i], kh, sacc[i][j]);
                        wmma::mma_sync(sacc[i][j], ql[i], kh, sacc[i][j]);
                        wmma::mma_sync(sacc[i][j], qh[i], kl, sacc[i][j]);
                    }
                }
            }
#pragma unroll
            for (int i = 0; i < 2; i++)
#pragma unroll
                for (int j = 0; j < 2; j++)
                    wmma::store_matrix_sync(sS + (wm * 32 + i * 16) * 72 + wn * 32 + j * 16,
                                            sacc[i][j], 72, wmma::mem_row_major);
        }
        __syncthreads();

        // ---- softmax (2 threads per row, 32 cols each, 2-pass) ----
        {
            const int qglob = q0 + row;
            float mx = -1e30f;
#pragma unroll
            for (int i = 0; i < 32; i++) {
                int c = sub * 32 + i;
                float s = sS[row * 72 + c] * SCALE;
                if (k0 + c > qglob) s = -1e30f;
                mx = fmaxf(mx, s);
            }
            mx = fmaxf(mx, __shfl_xor_sync(0xffffffffu, mx, 1));
            float m_new = fmaxf(m_i, mx);
            float alpha = __expf(m_i - m_new);

            float psum = 0.0f;
#pragma unroll
            for (int i = 0; i < 32; i++) {
                int c = sub * 32 + i;
                float s = sS[row * 72 + c] * SCALE;
                float p = (k0 + c > qglob) ? 0.0f : __expf(s - m_new);
                psum += p;
                bf16 ph, pl;
                split2(p, ph, pl);
                sPh[row * 72 + c] = ph;
                sPl[row * 72 + c] = pl;
            }
            psum += __shfl_xor_sync(0xffffffffu, psum, 1);

            l_i = l_i * alpha + psum;
            m_i = m_new;

#pragma unroll
            for (int i = 0; i < 32; i++)
                sO[row * 72 + sub * 32 + i] *= alpha;
        }
        __syncthreads();

        // ---- O += P @ V ----
        {
            wmma::fragment<wmma::accumulator, 16, 16, 16, float> oacc[2][2];
#pragma unroll
            for (int i = 0; i < 2; i++)
#pragma unroll
                for (int j = 0; j < 2; j++)
                    wmma::load_matrix_sync(oacc[i][j],
                        sO + (wm * 32 + i * 16) * 72 + wn * 32 + j * 16,
                        72, wmma::mem_row_major);
#pragma unroll
            for (int kk = 0; kk < 4; kk++) {
                wmma::fragment<wmma::matrix_a, 16, 16, 16, bf16, wmma::row_major> ph[2], pl[2];
#pragma unroll
                for (int i = 0; i < 2; i++) {
                    wmma::load_matrix_sync(ph[i], sPh + (wm * 32 + i * 16) * 72 + kk * 16, 72);
                    wmma::load_matrix_sync(pl[i], sPl + (wm * 32 + i * 16) * 72 + kk * 16, 72);
                }
#pragma unroll
                for (int j = 0; j < 2; j++) {
                    wmma::fragment<wmma::matrix_b, 16, 16, 16, bf16, wmma::row_major> vh, vl;
                    wmma::load_matrix_sync(vh, sVh + (kk * 16) * 72 + wn * 32 + j * 16, 72);
                    wmma::load_matrix_sync(vl, sVl + (kk * 16) * 72 + wn * 32 + j * 16, 72);
#pragma unroll
                    for (int i = 0; i < 2; i++) {
                        wmma::mma_sync(oacc[i][j], ph[i], vh, oacc[i][j]);
                        wmma::mma_sync(oacc[i][j], ph[i], vl, oacc[i][j]);
                        wmma::mma_sync(oacc[i][j], pl[i], vh, oacc[i][j]);
                    }
                }
            }
#pragma unroll
            for (int i = 0; i < 2; i++)
#pragma unroll
                for (int j = 0; j < 2; j++)
                    wmma::store_matrix_sync(sO + (wm * 32 + i * 16) * 72 + wn * 32 + j * 16,
                                            oacc[i][j], 72, wmma::mem_row_major);
        }
    }
    __syncthreads();

    // epilogue: normalize, split-write to concat layout [B,S,H*64]
    {
        float inv = 1.0f / l_i;
#pragma unroll
        for (int i = 0; i < 32; i++) {
            int c = sub * 32 + i;
            float v = sO[row * 72 + c] * inv;
            bf16 hh, ll;
            split2(v, hh, ll);
            size_t dst = ((size_t)(b * SS + q0 + row)) * DM + h * DVH + c;
            g_Ah[dst] = hh;
            g_Al[dst] = ll;
        }
    }
}

// ---------------------------------------------------------------------------
// launch
// ---------------------------------------------------------------------------
extern "C" void kernel_launch(void* const* d_in, const int* in_sizes, int n_in,
                              void* d_out, int out_size)
{
    const float* x  = (const float*)d_in[0];
    const float* Wq = (const float*)d_in[1];
    const float* Wk = (const float*)d_in[2];
    const float* Wv = (const float*)d_in[3];
    const float* Wo = (const float*)d_in[4];
    float* out = (float*)d_out;

    bf16 *xh, *xl, *wqh, *wql, *wkh, *wkl, *wvh, *wvl, *woh, *wol;
    cudaGetSymbolAddress((void**)&xh,  g_xh);  cudaGetSymbolAddress((void**)&xl,  g_xl);
    cudaGetSymbolAddress((void**)&wqh, g_Wqh); cudaGetSymbolAddress((void**)&wql, g_Wql);
    cudaGetSymbolAddress((void**)&wkh, g_Wkh); cudaGetSymbolAddress((void**)&wkl, g_Wkl);
    cudaGetSymbolAddress((void**)&wvh, g_Wvh); cudaGetSymbolAddress((void**)&wvl, g_Wvl);
    cudaGetSymbolAddress((void**)&woh, g_Woh); cudaGetSymbolAddress((void**)&wol, g_Wol);

    static int attr_set = 0;
    if (!attr_set) {
        cudaFuncSetAttribute(attn_wmma,
                             cudaFuncAttributeMaxDynamicSharedMemorySize,
                             ATTN_SMEM_BYTES);
        cudaFuncSetAttribute(qkv_wmma,
                             cudaFuncAttributeMaxDynamicSharedMemorySize,
                             QKV_SMEM_BYTES);
        cudaFuncSetAttribute(outproj_wmma,
                             cudaFuncAttributeMaxDynamicSharedMemorySize,
                             OUT_SMEM_BYTES);
        attr_set = 1;
    }

    // splits (elementwise; weights stay in [k][n] layout)
    {
        int n = MM * DIN;
        split_kernel<<<(n + 255) / 256, 256>>>(x, xh, xl, n);
        n = HH * DIN * DK;
        split_kernel<<<(n + 255) / 256, 256>>>(Wq, wqh, wql, n);
        split_kernel<<<(n + 255) / 256, 256>>>(Wk, wkh, wkl, n);
        split_kernel<<<(n + 255) / 256, 256>>>(Wv, wvh, wvl, n);
        n = DM * DM;
        split_kernel<<<(n + 255) / 256, 256>>>(Wo, woh, wol, n);
    }

    // fused QKV projection
    dim3 qgrid(MM / 128, HH);
    qkv_wmma<<<qgrid, 256, QKV_SMEM_BYTES>>>();

    // attention
    dim3 agrid(SS / 128, HH, BB);
    attn_wmma<<<agrid, 256, ATTN_SMEM_BYTES>>>();

    // output projection
    dim3 ogrid(MM / 128, DM / 128);
    outproj_wmma<<<ogrid, 256, OUT_SMEM_BYTES>>>(out);
}